// round 11
// baseline (speedup 1.0000x reference)
#include <cuda_runtime.h>
#include <cstdint>

// Problem constants
#define BB 4
#define SS 4096
#define DF 1024
#define HH 16
#define HD 64
#define SK 1024          // SS / STRIDE
#define STRIDE 4
#define BQ 128           // q rows per CTA
#define BK 64            // k cols per block
#define NBLK 16
#define NT 256
#define NQB 32           // q-blocks per (b,h)

// fragment-major, tf32-pre-rounded scratch
// K': per (b,h,kblk): [j(8)][t(8)][lane(32)][2] = 4096 floats
// V': per (b,h,kblk): [jt(8)][t(8)][lane(32)][2] = 4096 floats
// Q': per (b,h,qblk): [j(8)][warp(8)][lane(32)][4] = 8192 floats
__device__ float g_kf[BB * HH * NBLK * 4096];
__device__ float g_vf[BB * HH * NBLK * 4096];
__device__ float g_qf[BB * HH * NQB * 8192];

#define STG_FLOATS 4096        // one 64x64 stage
#define SM_TOTAL   65536       // 4 stages (K0,K1,V0,V1)

__device__ __forceinline__ uint32_t smem_u32(const void* p) {
    uint32_t a;
    asm("{ .reg .u64 t; cvta.to.shared.u64 t, %1; cvt.u32.u64 %0, t; }" : "=r"(a) : "l"(p));
    return a;
}
#define CP_ASYNC16(sa, gp) \
    asm volatile("cp.async.cg.shared.global [%0], [%1], 16;" :: "r"(sa), "l"(gp) : "memory")
#define CP_COMMIT() asm volatile("cp.async.commit_group;" ::: "memory")
#define CP_WAIT(N)  asm volatile("cp.async.wait_group %0;" :: "n"(N) : "memory")

__device__ __forceinline__ void mma_tf32(float c[4], const float a[4],
                                         float b0, float b1) {
    asm volatile(
        "mma.sync.aligned.m16n8k8.row.col.f32.tf32.tf32.f32 "
        "{%0,%1,%2,%3}, {%4,%5,%6,%7}, {%8,%9}, {%0,%1,%2,%3};"
        : "+f"(c[0]), "+f"(c[1]), "+f"(c[2]), "+f"(c[3])
        : "r"(__float_as_uint(a[0])), "r"(__float_as_uint(a[1])),
          "r"(__float_as_uint(a[2])), "r"(__float_as_uint(a[3])),
          "r"(__float_as_uint(b0)), "r"(__float_as_uint(b1)));
}
__device__ __forceinline__ float tf32_rn(float x) {
    return __uint_as_float((__float_as_uint(x) + 0x1000u) & 0xFFFFE000u);
}
__device__ __forceinline__ float ex2f(float x) {
    float y;
    asm("ex2.approx.f32 %0, %1;" : "=f"(y) : "f"(x));
    return y;
}

// ---- pre-kernel: gather K and V into fragment-major tf32 scratch ----
// K': frag (j*8+t): b0 = K[(kblk*64 + t*8 + gid)*STRIDE][j*8 + 2gc], b1 = col+1
// V': frag (jt*8+t): b0 = V[(kblk*64 + jt*8 + 2gc)*STRIDE][t*8 + gid], b1 = key row +1
__global__ __launch_bounds__(NT)
void shuffle_kv_kernel(const float* __restrict__ gk, const float* __restrict__ gv)
{
    int id = blockIdx.x * NT + threadIdx.x;
    int lane = id & 31, f1 = (id >> 5) & 7, f2 = (id >> 8) & 7;
    int kblk = (id >> 11) & 15, bh = id >> 15;
    int gid = lane >> 2, gc = lane & 3;
    int bi = bh >> 4, hc = (bh & 15) * HD;

    // K part (f1 = t row-group, f2 = j col-group)
    {
        int s = (kblk * 64 + f1 * 8 + gid) * STRIDE;
        int c = hc + f2 * 8 + 2 * gc;
        const float* src = gk + ((size_t)bi * SS + s) * DF + c;
        // mainloop reads kb[(j*8+t)*64 + lane*2] -> index [f2][f1][lane]
        size_t o = ((size_t)(id >> 11) * 64 + f2 * 8 + f1) * 64 + lane * 2;
        *(float2*)&g_kf[o] = make_float2(tf32_rn(src[0]), tf32_rn(src[1]));
    }
    // V part (f1 = t d-group, f2 = jt key-group)
    {
        int s = (kblk * 64 + f2 * 8 + 2 * gc) * STRIDE;
        int c = hc + f1 * 8 + gid;
        const float* src = gv + ((size_t)bi * SS + s) * DF + c;
        size_t o = ((size_t)(id >> 11) * 64 + f2 * 8 + f1) * 64 + lane * 2;
        *(float2*)&g_vf[o] =
            make_float2(tf32_rn(src[0]), tf32_rn(src[(size_t)STRIDE * DF]));
    }
}

// Q': a-frag {Q[r][c], Q[r+8][c], Q[r][c+1], Q[r+8][c+1]} * 0.125*log2(e), rn
__global__ __launch_bounds__(NT)
void shuffle_q_kernel(const float* __restrict__ gq)
{
    const float SCL = 0.125f * 1.44269504088896341f;
    int id = blockIdx.x * NT + threadIdx.x;
    int lane = id & 31, mg = (id >> 5) & 7, j = (id >> 8) & 7;
    int qblk = (id >> 11) & 31, bh = id >> 16;
    int gid = lane >> 2, gc = lane & 3;
    int r = qblk * BQ + mg * 16 + gid;
    int c = (bh & 15) * HD + j * 8 + 2 * gc;
    const float* src = gq + ((size_t)(bh >> 4) * SS + r) * DF + c;
    float4 o;
    o.x = tf32_rn(src[0] * SCL);
    o.y = tf32_rn(src[(size_t)8 * DF] * SCL);
    o.z = tf32_rn(src[1] * SCL);
    o.w = tf32_rn(src[(size_t)8 * DF + 1] * SCL);
    *(float4*)&g_qf[(size_t)id * 4] = o;
}

__global__ __launch_bounds__(NT, 2)
void attn_mma_kernel(float* __restrict__ out_a, float* __restrict__ out_w)
{
    extern __shared__ float sm[];
    const uint32_t smb = smem_u32(sm);

    const int tid = threadIdx.x, lane = tid & 31, warp = tid >> 5;
    const int gid = lane >> 2, gc = lane & 3;
    const int b = blockIdx.z, h = blockIdx.y, qblk = blockIdx.x;
    const int bh = b * HH + h;
    const int r0 = warp * 16 + gid;                  // warp owns q rows warp*16..+15

    const float* kf = g_kf + (size_t)bh * NBLK * 4096;
    const float* vf = g_vf + (size_t)bh * NBLK * 4096;
    const float* qf = g_qf + ((size_t)bh * NQB + qblk) * 8192;

    // ---- pre-issue K(0)->stage0, V(0)->stage2 ----
    {
        #pragma unroll
        for (int i = 0; i < 4; i++) {
            int cix = tid + i * NT;
            CP_ASYNC16(smb + cix * 16,                        kf + cix * 4);
            CP_ASYNC16(smb + 2 * (STG_FLOATS * 4) + cix * 16, vf + cix * 4);
        }
        CP_COMMIT();
    }

    // ---- Q fragments -> registers (coalesced LDG.128) ----
    float Qf[8][4];
    #pragma unroll
    for (int j = 0; j < 8; j++) {
        float4 qv = *(const float4*)&qf[(size_t)((j * 8 + warp) * 32 + lane) * 4];
        Qf[j][0] = qv.x; Qf[j][1] = qv.y; Qf[j][2] = qv.z; Qf[j][3] = qv.w;
    }

    float Acc[8][4];
    #pragma unroll
    for (int t = 0; t < 8; t++) {
        Acc[t][0] = 0.f; Acc[t][1] = 0.f; Acc[t][2] = 0.f; Acc[t][3] = 0.f;
    }
    float rs0 = 0.f, rs1 = 0.f;

    // ================= single pass: unnormalized w + PV =================
    for (int blk = 0; blk < NBLK; blk++) {
        CP_WAIT(0);
        __syncthreads();

        if (blk + 1 < NBLK) {
            const uint32_t ks_ = smb + ((blk + 1) & 1) * (STG_FLOATS * 4);
            const uint32_t vs_ = ks_ + 2 * (STG_FLOATS * 4);
            const float* ksrc = kf + (blk + 1) * STG_FLOATS;
            const float* vsrc = vf + (blk + 1) * STG_FLOATS;
            #pragma unroll
            for (int i = 0; i < 4; i++) {
                int cix = tid + i * NT;
                CP_ASYNC16(ks_ + cix * 16, ksrc + cix * 4);
                CP_ASYNC16(vs_ + cix * 16, vsrc + cix * 4);
            }
            CP_COMMIT();
        }

        const float* kb = sm + (blk & 1) * STG_FLOATS;
        const float* vb = sm + (2 + (blk & 1)) * STG_FLOATS;

        // ---- S = Q * K^T ----
        float S[8][4];
        #pragma unroll
        for (int t = 0; t < 8; t++) {
            S[t][0] = 0.f; S[t][1] = 0.f; S[t][2] = 0.f; S[t][3] = 0.f;
        }
        #pragma unroll
        for (int j = 0; j < 8; j++) {
            #pragma unroll
            for (int t = 0; t < 8; t++) {
                float2 bk = *(const float2*)&kb[(j * 8 + t) * 64 + lane * 2];
                mma_tf32(S[t], Qf[j], bk.x, bk.y);
            }
        }

        // ---- p = 2^s, row-sum, unnormalized w -> gmem; S becomes P ----
        float* wr0 = out_w + ((size_t)bh * SS + qblk * BQ + r0) * SK + blk * BK;
        float* wr1 = wr0 + (size_t)8 * SK;
        #pragma unroll
        for (int t = 0; t < 8; t++) {
            float p0 = ex2f(S[t][0]), p1 = ex2f(S[t][1]);
            float p2 = ex2f(S[t][2]), p3 = ex2f(S[t][3]);
            rs0 += p0 + p1;
            rs1 += p2 + p3;
            int col = t * 8 + 2 * gc;
            *(float2*)&wr0[col] = make_float2(p0, p1);
            *(float2*)&wr1[col] = make_float2(p2, p3);
            S[t][0] = p0; S[t][1] = p1; S[t][2] = p2; S[t][3] = p3;
        }

        // ---- Acc += P * V  (C->A feed; V' fragment-major float2) ----
        #pragma unroll
        for (int jt = 0; jt < 8; jt++) {
            float ap[4];
            ap[0] = S[jt][0]; ap[1] = S[jt][2];
            ap[2] = S[jt][1]; ap[3] = S[jt][3];
            #pragma unroll
            for (int t = 0; t < 8; t++) {
                float2 bv = *(const float2*)&vb[(jt * 8 + t) * 64 + lane * 2];
                mma_tf32(Acc[t], ap, bv.x, bv.y);
            }
        }
    }

    // ---- quad reduce -> per-row inverses (warp-local) ----
    rs0 += __shfl_xor_sync(0xFFFFFFFFu, rs0, 1);
    rs0 += __shfl_xor_sync(0xFFFFFFFFu, rs0, 2);
    rs1 += __shfl_xor_sync(0xFFFFFFFFu, rs1, 1);
    rs1 += __shfl_xor_sync(0xFFFFFFFFu, rs1, 2);
    const float inv0 = 1.0f / rs0, inv1 = 1.0f / rs1;

    // stash inverses for the rescale loop (stage smem is dead now)
    __syncthreads();
    float* rsb = sm;
    if (gc == 0) { rsb[r0] = inv0; rsb[r0 + 8] = inv1; }

    // ---- a: normalize accumulators and store ----
    {
        float* ar0 = out_a + ((size_t)(b * SS + qblk * BQ + r0)) * DF + h * HD;
        float* ar1 = ar0 + (size_t)8 * DF;
        #pragma unroll
        for (int t = 0; t < 8; t++) {
            int col = t * 8 + 2 * gc;
            *(float2*)&ar0[col] = make_float2(Acc[t][0] * inv0, Acc[t][1] * inv0);
            *(float2*)&ar1[col] = make_float2(Acc[t][2] * inv1, Acc[t][3] * inv1);
        }
    }
    __syncthreads();   // rsb visible; all w stores of this CTA done & visible

    // ---- w: rescale in place (own slab; mostly L2-resident) ----
    {
        float* wslab = out_w + ((size_t)bh * SS + qblk * BQ) * SK;
        #pragma unroll 4
        for (int idx = tid; idx < BQ * (SK / 4); idx += NT) {
            int r = idx >> 8, c4 = (idx & 255) << 2;
            float il = rsb[r];
            float4 t = *(float4*)&wslab[(size_t)r * SK + c4];
            t.x *= il; t.y *= il; t.z *= il; t.w *= il;
            *(float4*)&wslab[(size_t)r * SK + c4] = t;
        }
    }
}

extern "C" void kernel_launch(void* const* d_in, const int* in_sizes, int n_in,
                              void* d_out, int out_size)
{
    (void)in_sizes; (void)n_in; (void)out_size;
    const float* q = (const float*)d_in[0];
    const float* k = (const float*)d_in[1];
    const float* v = (const float*)d_in[2];

    float* out_a = (float*)d_out;
    float* out_w = out_a + (size_t)BB * SS * DF;  // w follows a

    shuffle_kv_kernel<<<(BB * HH * NBLK * 2048) / NT, NT>>>(k, v);
    shuffle_q_kernel<<<(BB * HH * NQB * 2048) / NT, NT>>>(q);

    cudaFuncSetAttribute(attn_mma_kernel,
                         cudaFuncAttributeMaxDynamicSharedMemorySize, SM_TOTAL);
    dim3 grid(NQB, HH, BB);   // (32, 16, 4) = 2048 CTAs
    attn_mma_kernel<<<grid, NT, SM_TOTAL>>>(out_a, out_w);
}

// round 13
// speedup vs baseline: 1.4839x; 1.4839x over previous
#include <cuda_runtime.h>
#include <cstdint>

// Problem constants
#define BB 4
#define SS 4096
#define DF 1024
#define HH 16
#define HD 64
#define SK 1024          // SS / STRIDE
#define STRIDE 4
#define BQ 128           // q rows per CTA
#define BK 64            // k cols per block
#define NBLK 16
#define NT 256
#define NQB 32           // q-blocks per (b,h)

// fragment-major, tf32-pre-rounded scratch (layouts verified R10/R11)
__device__ float g_kf[BB * HH * NBLK * 4096];
__device__ float g_vf[BB * HH * NBLK * 4096];
__device__ float g_qf[BB * HH * NQB * 8192];

#define STG 4096                   // floats per K/V stage
#define SM_QOFF (4 * STG)          // Q stage at float offset 16384
#define SM_TOTAL ((4 * STG + 8192) * 4)   // 98304 bytes

__device__ __forceinline__ uint32_t smem_u32(const void* p) {
    uint32_t a;
    asm("{ .reg .u64 t; cvta.to.shared.u64 t, %1; cvt.u32.u64 %0, t; }" : "=r"(a) : "l"(p));
    return a;
}
#define CP_ASYNC16(sa, gp) \
    asm volatile("cp.async.cg.shared.global [%0], [%1], 16;" :: "r"(sa), "l"(gp) : "memory")
#define CP_COMMIT() asm volatile("cp.async.commit_group;" ::: "memory")
#define CP_WAIT(N)  asm volatile("cp.async.wait_group %0;" :: "n"(N) : "memory")

__device__ __forceinline__ void mma_tf32(float c[4], float a0, float a1, float a2,
                                         float a3, float b0, float b1) {
    asm volatile(
        "mma.sync.aligned.m16n8k8.row.col.f32.tf32.tf32.f32 "
        "{%0,%1,%2,%3}, {%4,%5,%6,%7}, {%8,%9}, {%0,%1,%2,%3};"
        : "+f"(c[0]), "+f"(c[1]), "+f"(c[2]), "+f"(c[3])
        : "r"(__float_as_uint(a0)), "r"(__float_as_uint(a1)),
          "r"(__float_as_uint(a2)), "r"(__float_as_uint(a3)),
          "r"(__float_as_uint(b0)), "r"(__float_as_uint(b1)));
}
__device__ __forceinline__ float tf32_rn(float x) {
    return __uint_as_float((__float_as_uint(x) + 0x1000u) & 0xFFFFE000u);
}
__device__ __forceinline__ float ex2f(float x) {
    float y;
    asm("ex2.approx.f32 %0, %1;" : "=f"(y) : "f"(x));
    return y;
}

// ---- pre-kernels (verbatim from R11; verified) ----
__global__ __launch_bounds__(NT)
void shuffle_kv_kernel(const float* __restrict__ gk, const float* __restrict__ gv)
{
    int id = blockIdx.x * NT + threadIdx.x;
    int lane = id & 31, f1 = (id >> 5) & 7, f2 = (id >> 8) & 7;
    int gid = lane >> 2, gc = lane & 3;
    int kblk = (id >> 11) & 15, bh = id >> 15;
    int bi = bh >> 4, hc = (bh & 15) * HD;
    {
        int s = (kblk * 64 + f1 * 8 + gid) * STRIDE;
        int c = hc + f2 * 8 + 2 * gc;
        const float* src = gk + ((size_t)bi * SS + s) * DF + c;
        size_t o = ((size_t)(id >> 11) * 64 + f2 * 8 + f1) * 64 + lane * 2;
        *(float2*)&g_kf[o] = make_float2(tf32_rn(src[0]), tf32_rn(src[1]));
    }
    {
        int s = (kblk * 64 + f2 * 8 + 2 * gc) * STRIDE;
        int c = hc + f1 * 8 + gid;
        const float* src = gv + ((size_t)bi * SS + s) * DF + c;
        size_t o = ((size_t)(id >> 11) * 64 + f2 * 8 + f1) * 64 + lane * 2;
        *(float2*)&g_vf[o] =
            make_float2(tf32_rn(src[0]), tf32_rn(src[(size_t)STRIDE * DF]));
    }
}
__global__ __launch_bounds__(NT)
void shuffle_q_kernel(const float* __restrict__ gq)
{
    const float SCL = 0.125f * 1.44269504088896341f;
    int id = blockIdx.x * NT + threadIdx.x;
    int lane = id & 31, mg = (id >> 5) & 7, j = (id >> 8) & 7;
    int qblk = (id >> 11) & 31, bh = id >> 16;
    int gid = lane >> 2, gc = lane & 3;
    int r = qblk * BQ + mg * 16 + gid;
    int c = (bh & 15) * HD + j * 8 + 2 * gc;
    const float* src = gq + ((size_t)(bh >> 4) * SS + r) * DF + c;
    float4 o;
    o.x = tf32_rn(src[0] * SCL);
    o.y = tf32_rn(src[(size_t)8 * DF] * SCL);
    o.z = tf32_rn(src[1] * SCL);
    o.w = tf32_rn(src[(size_t)8 * DF + 1] * SCL);
    *(float4*)&g_qf[(size_t)id * 4] = o;
}

__global__ __launch_bounds__(NT, 2)
void attn_mma_kernel(float* __restrict__ out_a, float* __restrict__ out_w)
{
    extern __shared__ float sm[];
    const uint32_t smb = smem_u32(sm);

    const int tid = threadIdx.x, lane = tid & 31, warp = tid >> 5;
    const int gid = lane >> 2, gc = lane & 3;
    const int mg = warp >> 1, ng = warp & 1;         // 4 m-groups x 2 k-slices
    const int b = blockIdx.z, hh = blockIdx.y, qblk = blockIdx.x;
    const int bh = b * HH + hh;

    const float* kf = g_kf + (size_t)bh * NBLK * 4096;
    const float* vf = g_vf + (size_t)bh * NBLK * 4096;
    const float* qf = g_qf + ((size_t)bh * NQB + qblk) * 8192;

    // ---- pre-issue: Q stage (group 0), K blocks 0..2 (groups 1..3) ----
    #pragma unroll
    for (int i = 0; i < 8; i++) {
        int cix = tid + i * NT;
        CP_ASYNC16(smb + (SM_QOFF + cix * 4) * 4, qf + cix * 4);
    }
    CP_COMMIT();
    #pragma unroll
    for (int p = 0; p < 3; p++) {
        #pragma unroll
        for (int i = 0; i < 4; i++) {
            int cix = tid + i * NT;
            CP_ASYNC16(smb + p * (STG * 4) + cix * 16, kf + p * STG + cix * 4);
        }
        CP_COMMIT();
    }

    CP_WAIT(3);          // Q stage resident (K0..K2 still in flight)
    __syncthreads();

    // ---- pass-1 Q fragments -> registers (m32: granules 2mg, 2mg+1) ----
    float Qf[2][8][4];
    #pragma unroll
    for (int j = 0; j < 8; j++) {
        #pragma unroll
        for (int u = 0; u < 2; u++) {
            float4 qv = *(const float4*)&sm[SM_QOFF + ((j * 8 + 2 * mg + u) * 32 + lane) * 4];
            Qf[u][j][0] = qv.x; Qf[u][j][1] = qv.y;
            Qf[u][j][2] = qv.z; Qf[u][j][3] = qv.w;
        }
    }

    float rs[4] = {0.f, 0.f, 0.f, 0.f};

    // ================= PASS 1: row sums (K ring, 4 stages) =================
    for (int blk = 0; blk < NBLK; blk++) {
        if      (blk < NBLK - 2)  CP_WAIT(2);
        else if (blk == NBLK - 2) CP_WAIT(1);
        else                      CP_WAIT(0);
        __syncthreads();

        if (blk + 3 < NBLK) {
            const uint32_t st = smb + ((blk + 3) & 3) * (STG * 4);
            const float* src = kf + (blk + 3) * STG;
            #pragma unroll
            for (int i = 0; i < 4; i++) {
                int cix = tid + i * NT;
                CP_ASYNC16(st + cix * 16, src + cix * 4);
            }
            CP_COMMIT();
        }

        const float* kb = sm + (blk & 3) * STG;

        float S[2][4][4];
        #pragma unroll
        for (int u = 0; u < 2; u++)
            #pragma unroll
            for (int t = 0; t < 4; t++) {
                S[u][t][0] = 0.f; S[u][t][1] = 0.f; S[u][t][2] = 0.f; S[u][t][3] = 0.f;
            }
        #pragma unroll
        for (int j = 0; j < 8; j++) {
            #pragma unroll
            for (int t = 0; t < 4; t++) {
                float2 bk = *(const float2*)&kb[(j * 8 + ng * 4 + t) * 64 + lane * 2];
                mma_tf32(S[0][t], Qf[0][j][0], Qf[0][j][1], Qf[0][j][2], Qf[0][j][3], bk.x, bk.y);
                mma_tf32(S[1][t], Qf[1][j][0], Qf[1][j][1], Qf[1][j][2], Qf[1][j][3], bk.x, bk.y);
            }
        }
        #pragma unroll
        for (int u = 0; u < 2; u++)
            #pragma unroll
            for (int t = 0; t < 4; t++) {
                rs[2 * u]     += ex2f(S[u][t][0]) + ex2f(S[u][t][1]);
                rs[2 * u + 1] += ex2f(S[u][t][2]) + ex2f(S[u][t][3]);
            }
    }

    // quad reduce (k within warp), then cross-ng via smem table
    #pragma unroll
    for (int i = 0; i < 4; i++) {
        rs[i] += __shfl_xor_sync(0xFFFFFFFFu, rs[i], 1);
        rs[i] += __shfl_xor_sync(0xFFFFFFFFu, rs[i], 2);
    }
    float* rsb = sm;   // stage 0 is dead (last read blk 12; barriers passed)
    if (gc == 0) {
        int rbase = mg * 32 + gid;
        rsb[ng * 128 + rbase]      = rs[0];
        rsb[ng * 128 + rbase + 8]  = rs[1];
        rsb[ng * 128 + rbase + 16] = rs[2];
        rsb[ng * 128 + rbase + 24] = rs[3];
    }
    __syncthreads();
    float inv[4];
    {
        int rbase = mg * 32 + gid;
        inv[0] = 1.0f / (rsb[rbase]      + rsb[128 + rbase]);
        inv[1] = 1.0f / (rsb[rbase + 8]  + rsb[128 + rbase + 8]);
        inv[2] = 1.0f / (rsb[rbase + 16] + rsb[128 + rbase + 16]);
        inv[3] = 1.0f / (rsb[rbase + 24] + rsb[128 + rbase + 24]);
    }
    __syncthreads();   // all reads done before stage0 is overwritten

    // ---- pass-2 pre-issue: K0 -> stage0, V0 -> stage2 ----
    {
        #pragma unroll
        for (int i = 0; i < 4; i++) {
            int cix = tid + i * NT;
            CP_ASYNC16(smb + cix * 16,                 kf + cix * 4);
            CP_ASYNC16(smb + 2 * (STG * 4) + cix * 16, vf + cix * 4);
        }
        CP_COMMIT();
    }

    float Acc[2][8][4];
    #pragma unroll
    for (int u = 0; u < 2; u++)
        #pragma unroll
        for (int t = 0; t < 8; t++) {
            Acc[u][t][0] = 0.f; Acc[u][t][1] = 0.f; Acc[u][t][2] = 0.f; Acc[u][t][3] = 0.f;
        }

    // ================= PASS 2: normalized w + PV =================
    for (int blk = 0; blk < NBLK; blk++) {
        CP_WAIT(0);
        __syncthreads();

        if (blk + 1 < NBLK) {
            const uint32_t ks_ = smb + ((blk + 1) & 1) * (STG * 4);
            const uint32_t vs_ = ks_ + 2 * (STG * 4);
            const float* ksrc = kf + (blk + 1) * STG;
            const float* vsrc = vf + (blk + 1) * STG;
            #pragma unroll
            for (int i = 0; i < 4; i++) {
                int cix = tid + i * NT;
                CP_ASYNC16(ks_ + cix * 16, ksrc + cix * 4);
                CP_ASYNC16(vs_ + cix * 16, vsrc + cix * 4);
            }
            CP_COMMIT();
        }

        const float* kb = sm + (blk & 1) * STG;
        const float* vb = sm + (2 + (blk & 1)) * STG;

        // ---- S = Q * K^T  (Q A-frags re-read from smem via LDS.128) ----
        float S[2][4][4];
        #pragma unroll
        for (int u = 0; u < 2; u++)
            #pragma unroll
            for (int t = 0; t < 4; t++) {
                S[u][t][0] = 0.f; S[u][t][1] = 0.f; S[u][t][2] = 0.f; S[u][t][3] = 0.f;
            }
        #pragma unroll
        for (int j = 0; j < 8; j++) {
            float4 qa0 = *(const float4*)&sm[SM_QOFF + ((j * 8 + 2 * mg)     * 32 + lane) * 4];
            float4 qa1 = *(const float4*)&sm[SM_QOFF + ((j * 8 + 2 * mg + 1) * 32 + lane) * 4];
            #pragma unroll
            for (int t = 0; t < 4; t++) {
                float2 bk = *(const float2*)&kb[(j * 8 + ng * 4 + t) * 64 + lane * 2];
                mma_tf32(S[0][t], qa0.x, qa0.y, qa0.z, qa0.w, bk.x, bk.y);
                mma_tf32(S[1][t], qa1.x, qa1.y, qa1.z, qa1.w, bk.x, bk.y);
            }
        }

        // ---- normalized w -> gmem; S becomes normalized P ----
        float* wbase = out_w + ((size_t)bh * SS + qblk * BQ + mg * 32 + gid) * SK
                     + blk * BK + ng * 32;
        #pragma unroll
        for (int u = 0; u < 2; u++) {
            float* wr0 = wbase + (size_t)(u * 16) * SK;
            float* wr1 = wr0 + (size_t)8 * SK;
            #pragma unroll
            for (int t = 0; t < 4; t++) {
                float p0 = ex2f(S[u][t][0]) * inv[2 * u];
                float p1 = ex2f(S[u][t][1]) * inv[2 * u];
                float p2 = ex2f(S[u][t][2]) * inv[2 * u + 1];
                float p3 = ex2f(S[u][t][3]) * inv[2 * u + 1];
                int col = t * 8 + 2 * gc;
                *(float2*)&wr0[col] = make_float2(p0, p1);
                *(float2*)&wr1[col] = make_float2(p2, p3);
                S[u][t][0] = p0; S[u][t][1] = p1; S[u][t][2] = p2; S[u][t][3] = p3;
            }
        }

        // ---- Acc += P * V  (C->A feed; warp's own k-slice) ----
        #pragma unroll
        for (int jt = 0; jt < 4; jt++) {
            float a00 = S[0][jt][0], a01 = S[0][jt][2], a02 = S[0][jt][1], a03 = S[0][jt][3];
            float a10 = S[1][jt][0], a11 = S[1][jt][2], a12 = S[1][jt][1], a13 = S[1][jt][3];
            #pragma unroll
            for (int t = 0; t < 8; t++) {
                float2 bv = *(const float2*)&vb[((ng * 4 + jt) * 8 + t) * 64 + lane * 2];
                mma_tf32(Acc[0][t], a00, a01, a02, a03, bv.x, bv.y);
                mma_tf32(Acc[1][t], a10, a11, a12, a13, bv.x, bv.y);
            }
        }
    }

    // ---- epilogue: combine ng partners' Acc, store a (ALREADY normalized) ----
    __syncthreads();   // all warps done with stages
    float* ab = sm;    // stride 65 -> conflict-free scalar, 33.3KB < stages
    if (ng == 1) {
        float* p = ab + (mg * 32 + lane) * 65;
        #pragma unroll
        for (int u = 0; u < 2; u++)
            #pragma unroll
            for (int t = 0; t < 8; t++) {
                p[(u * 8 + t) * 4 + 0] = Acc[u][t][0];
                p[(u * 8 + t) * 4 + 1] = Acc[u][t][1];
                p[(u * 8 + t) * 4 + 2] = Acc[u][t][2];
                p[(u * 8 + t) * 4 + 3] = Acc[u][t][3];
            }
    }
    __syncthreads();
    if (ng == 0) {
        const float* p = ab + (mg * 32 + lane) * 65;
        #pragma unroll
        for (int u = 0; u < 2; u++) {
            float* ar0 = out_a + ((size_t)(b * SS + qblk * BQ + mg * 32 + u * 16 + gid)) * DF
                       + hh * HD;
            float* ar1 = ar0 + (size_t)8 * DF;
            #pragma unroll
            for (int t = 0; t < 8; t++) {
                float o0 = p[(u * 8 + t) * 4 + 0], o1 = p[(u * 8 + t) * 4 + 1];
                float o2 = p[(u * 8 + t) * 4 + 2], o3 = p[(u * 8 + t) * 4 + 3];
                int col = t * 8 + 2 * gc;
                // P was normalized before PV -> Acc is already normalized
                *(float2*)&ar0[col] = make_float2(Acc[u][t][0] + o0, Acc[u][t][1] + o1);
                *(float2*)&ar1[col] = make_float2(Acc[u][t][2] + o2, Acc[u][t][3] + o3);
            }
        }
    }
}

extern "C" void kernel_launch(void* const* d_in, const int* in_sizes, int n_in,
                              void* d_out, int out_size)
{
    (void)in_sizes; (void)n_in; (void)out_size;
    const float* q = (const float*)d_in[0];
    const float* k = (const float*)d_in[1];
    const float* v = (const float*)d_in[2];

    float* out_a = (float*)d_out;
    float* out_w = out_a + (size_t)BB * SS * DF;  // w follows a

    shuffle_kv_kernel<<<(BB * HH * NBLK * 2048) / NT, NT>>>(k, v);
    shuffle_q_kernel<<<(BB * HH * NQB * 2048) / NT, NT>>>(q);

    cudaFuncSetAttribute(attn_mma_kernel,
                         cudaFuncAttributeMaxDynamicSharedMemorySize, SM_TOTAL);
    dim3 grid(NQB, HH, BB);   // (32, 16, 4) = 2048 CTAs
    attn_mma_kernel<<<grid, NT, SM_TOTAL>>>(out_a, out_w);
}

// round 14
// speedup vs baseline: 2.4547x; 1.6543x over previous
#include <cuda_runtime.h>
#include <cuda_fp16.h>
#include <cstdint>

// Problem constants
#define BB 4
#define SS 4096
#define DF 1024
#define HH 16
#define HD 64
#define SK 1024          // SS / STRIDE
#define STRIDE 4
#define BQ 128           // q rows per CTA
#define BK 64            // k cols per block
#define NBLK 16
#define NT 256
#define NQB 32           // q-blocks per (b,h)

// fp16 fragment-major scratch (packed half2 in uint)
// Kh: per (bh,kblk): [chunk(4)][ntile(8)][lane(32)] uint2  -> 1024 uint2 = 8KB
// Vh: per (bh,kblk): [chunk(4)][dtile(8)][lane(32)] uint2  -> 8KB
// Qh: per (bh,qblk): [chunk(4)][warp(8)][lane(32)]  uint4  -> 16KB
__device__ uint2 g_kh[BB * HH * NBLK * 1024];
__device__ uint2 g_vh[BB * HH * NBLK * 1024];
__device__ uint4 g_qh[BB * HH * NQB * 1024];

#define STGB 8192                 // bytes per stage
#define SM_TOTAL 32768            // pass1: ring of 4; pass2: K0,K1,V0,V1

__device__ __forceinline__ uint32_t smem_u32(const void* p) {
    uint32_t a;
    asm("{ .reg .u64 t; cvta.to.shared.u64 t, %1; cvt.u32.u64 %0, t; }" : "=r"(a) : "l"(p));
    return a;
}
#define CP_ASYNC16(sa, gp) \
    asm volatile("cp.async.cg.shared.global [%0], [%1], 16;" :: "r"(sa), "l"(gp) : "memory")
#define CP_COMMIT() asm volatile("cp.async.commit_group;" ::: "memory")
#define CP_WAIT(N)  asm volatile("cp.async.wait_group %0;" :: "n"(N) : "memory")

// C += A * B, m16n8k16 fp16 inputs, fp32 accumulate
__device__ __forceinline__ void mma_f16(float c[4], uint32_t a0, uint32_t a1,
                                        uint32_t a2, uint32_t a3,
                                        uint32_t b0, uint32_t b1) {
    asm volatile(
        "mma.sync.aligned.m16n8k16.row.col.f32.f16.f16.f32 "
        "{%0,%1,%2,%3}, {%4,%5,%6,%7}, {%8,%9}, {%0,%1,%2,%3};"
        : "+f"(c[0]), "+f"(c[1]), "+f"(c[2]), "+f"(c[3])
        : "r"(a0), "r"(a1), "r"(a2), "r"(a3), "r"(b0), "r"(b1));
}
__device__ __forceinline__ uint32_t packh2(float a, float b) {
    __half2 h = __floats2half2_rn(a, b);
    return *reinterpret_cast<uint32_t*>(&h);
}
__device__ __forceinline__ float ex2f(float x) {
    float y;
    asm("ex2.approx.f32 %0, %1;" : "=f"(y) : "f"(x));
    return y;
}

// ---- pre-kernel: K and V into fp16 fragment-major scratch ----
// thread id bits: lane(5) | ntile/dtile t(3) | chunk(2) | kblk(4) | bh(6)
__global__ __launch_bounds__(NT)
void shuffle_kvh_kernel(const float* __restrict__ gk, const float* __restrict__ gv)
{
    int id = blockIdx.x * NT + threadIdx.x;
    int lane = id & 31, t = (id >> 5) & 7, chunk = (id >> 8) & 3;
    int kblk = (id >> 10) & 15, bh = id >> 14;
    int gid = lane >> 2, gc = lane & 3;
    int bi = bh >> 4, hc = (bh & 15) * HD;
    size_t o = (size_t)(id >> 10) * 1024 + (chunk * 8 + t) * 32 + lane;

    // K: b-frag {K[key][f+2gc], K[key][f+2gc+1]} lo/hi, and +8 pair
    {
        int srow = kblk * 64 + t * 8 + gid;                  // key (n) index
        const float* src = gk + ((size_t)bi * SS + (size_t)srow * STRIDE) * DF
                         + hc + chunk * 16 + 2 * gc;
        g_kh[o] = make_uint2(packh2(src[0], src[1]), packh2(src[8], src[9]));
    }
    // V: b-frag {V[key0][d], V[key0+1][d]} lo/hi, and keys +8
    {
        int key0 = kblk * 64 + chunk * 16 + 2 * gc;
        const float* src = gv + ((size_t)bi * SS + (size_t)key0 * STRIDE) * DF
                         + hc + t * 8 + gid;
        const size_t R = (size_t)STRIDE * DF;
        g_vh[o] = make_uint2(packh2(src[0], src[R]),
                             packh2(src[8 * R], src[9 * R]));
    }
}

// ---- pre-kernel: Q into fp16 a-frags (scaled by 0.125*log2 e) ----
// id bits: lane(5) | warp(3) | chunk(2) | qblk(5) | bh(6)
__global__ __launch_bounds__(NT)
void shuffle_qh_kernel(const float* __restrict__ gq)
{
    const float SCL = 0.125f * 1.44269504088896341f;
    int id = blockIdx.x * NT + threadIdx.x;
    int lane = id & 31, warp = (id >> 5) & 7, chunk = (id >> 8) & 3;
    int qblk = (id >> 10) & 31, bh = id >> 15;
    int gid = lane >> 2, gc = lane & 3;
    int r = qblk * BQ + warp * 16 + gid;
    const float* src = gq + ((size_t)(bh >> 4) * SS + r) * DF
                     + (bh & 15) * HD + chunk * 16 + 2 * gc;
    const size_t R8 = (size_t)8 * DF;
    uint32_t a0 = packh2(src[0] * SCL,      src[1] * SCL);
    uint32_t a1 = packh2(src[R8] * SCL,     src[R8 + 1] * SCL);
    uint32_t a2 = packh2(src[8] * SCL,      src[9] * SCL);
    uint32_t a3 = packh2(src[R8 + 8] * SCL, src[R8 + 9] * SCL);
    g_qh[(size_t)(id >> 10) * 1024 + (chunk * 8 + warp) * 32 + lane] =
        make_uint4(a0, a1, a2, a3);
}

__global__ __launch_bounds__(NT, 2)
void attn_mma_kernel(float* __restrict__ out_a, float* __restrict__ out_w)
{
    extern __shared__ char sm[];
    const uint32_t smb = smem_u32(sm);

    const int tid = threadIdx.x, lane = tid & 31, warp = tid >> 5;
    const int gid = lane >> 2, gc = lane & 3;
    const int b = blockIdx.z, hh = blockIdx.y, qblk = blockIdx.x;
    const int bh = b * HH + hh;

    const uint2* kh = g_kh + (size_t)bh * NBLK * 1024;
    const uint2* vh = g_vh + (size_t)bh * NBLK * 1024;
    const uint4* qh = g_qh + ((size_t)bh * NQB + qblk) * 1024;

    // ---- pass1 pre-issue: K blocks 0..2 into ring stages 0..2 (8KB each) ----
    #pragma unroll
    for (int p = 0; p < 3; p++) {
        const char* src = (const char*)(kh + p * 1024);
        #pragma unroll
        for (int i = 0; i < 2; i++) {
            int cix = tid + i * NT;
            CP_ASYNC16(smb + p * STGB + cix * 16, src + cix * 16);
        }
        CP_COMMIT();
    }

    // ---- Q fragments -> registers (4 chunks x uint4) ----
    uint4 Qh[4];
    #pragma unroll
    for (int j = 0; j < 4; j++)
        Qh[j] = qh[(j * 8 + warp) * 32 + lane];

    float rs0 = 0.f, rs1 = 0.f;

    // ================= PASS 1: row sums (K ring, 4 stages) =================
    for (int blk = 0; blk < NBLK; blk++) {
        if      (blk < NBLK - 2)  CP_WAIT(2);
        else if (blk == NBLK - 2) CP_WAIT(1);
        else                      CP_WAIT(0);
        __syncthreads();

        if (blk + 3 < NBLK) {
            const char* src = (const char*)(kh + (blk + 3) * 1024);
            const uint32_t st = smb + ((blk + 3) & 3) * STGB;
            #pragma unroll
            for (int i = 0; i < 2; i++) {
                int cix = tid + i * NT;
                CP_ASYNC16(st + cix * 16, src + cix * 16);
            }
            CP_COMMIT();
        }

        const uint2* kb = (const uint2*)(sm + (blk & 3) * STGB);

        float S[8][4];
        #pragma unroll
        for (int t = 0; t < 8; t++) {
            S[t][0] = 0.f; S[t][1] = 0.f; S[t][2] = 0.f; S[t][3] = 0.f;
        }
        #pragma unroll
        for (int j = 0; j < 4; j++) {
            #pragma unroll
            for (int t = 0; t < 8; t++) {
                uint2 bk = kb[(j * 8 + t) * 32 + lane];
                mma_f16(S[t], Qh[j].x, Qh[j].y, Qh[j].z, Qh[j].w, bk.x, bk.y);
            }
        }
        #pragma unroll
        for (int t = 0; t < 8; t++) {
            rs0 += ex2f(S[t][0]) + ex2f(S[t][1]);
            rs1 += ex2f(S[t][2]) + ex2f(S[t][3]);
        }
    }

    // quad reduce (warp-local; all 4 lanes of each quad get totals)
    rs0 += __shfl_xor_sync(0xFFFFFFFFu, rs0, 1);
    rs0 += __shfl_xor_sync(0xFFFFFFFFu, rs0, 2);
    rs1 += __shfl_xor_sync(0xFFFFFFFFu, rs1, 1);
    rs1 += __shfl_xor_sync(0xFFFFFFFFu, rs1, 2);
    const float inv0 = 1.0f / rs0, inv1 = 1.0f / rs1;

    // ---- pass2 pre-issue: K0 -> stage0 (0-8KB), V0 -> stage2 (16-24KB) ----
    // safe: ring stages 0..2 dead for all warps (last reads blk<=14, behind blk15 barrier)
    {
        #pragma unroll
        for (int i = 0; i < 2; i++) {
            int cix = tid + i * NT;
            CP_ASYNC16(smb + cix * 16,            (const char*)kh + cix * 16);
            CP_ASYNC16(smb + 2 * STGB + cix * 16, (const char*)vh + cix * 16);
        }
        CP_COMMIT();
    }

    float Acc[8][4];
    #pragma unroll
    for (int t = 0; t < 8; t++) {
        Acc[t][0] = 0.f; Acc[t][1] = 0.f; Acc[t][2] = 0.f; Acc[t][3] = 0.f;
    }

    // ================= PASS 2: normalized w + PV =================
    for (int blk = 0; blk < NBLK; blk++) {
        CP_WAIT(0);
        __syncthreads();

        if (blk + 1 < NBLK) {
            const uint32_t ks_ = smb + ((blk + 1) & 1) * STGB;
            const uint32_t vs_ = ks_ + 2 * STGB;
            const char* ksrc = (const char*)(kh + (blk + 1) * 1024);
            const char* vsrc = (const char*)(vh + (blk + 1) * 1024);
            #pragma unroll
            for (int i = 0; i < 2; i++) {
                int cix = tid + i * NT;
                CP_ASYNC16(ks_ + cix * 16, ksrc + cix * 16);
                CP_ASYNC16(vs_ + cix * 16, vsrc + cix * 16);
            }
            CP_COMMIT();
        }

        const uint2* kb = (const uint2*)(sm + (blk & 1) * STGB);
        const uint2* vb = (const uint2*)(sm + (2 + (blk & 1)) * STGB);

        // ---- S = Q * K^T  (identical op order to pass 1 -> same bits) ----
        float S[8][4];
        #pragma unroll
        for (int t = 0; t < 8; t++) {
            S[t][0] = 0.f; S[t][1] = 0.f; S[t][2] = 0.f; S[t][3] = 0.f;
        }
        #pragma unroll
        for (int j = 0; j < 4; j++) {
            #pragma unroll
            for (int t = 0; t < 8; t++) {
                uint2 bk = kb[(j * 8 + t) * 32 + lane];
                mma_f16(S[t], Qh[j].x, Qh[j].y, Qh[j].z, Qh[j].w, bk.x, bk.y);
            }
        }

        // ---- normalized w -> gmem; P packed to fp16 a-frags ----
        float* wr0 = out_w + ((size_t)bh * SS + qblk * BQ + warp * 16 + gid) * SK
                   + blk * BK;
        float* wr1 = wr0 + (size_t)8 * SK;
        uint32_t Ph[8][2];
        #pragma unroll
        for (int t = 0; t < 8; t++) {
            float p0 = ex2f(S[t][0]) * inv0, p1 = ex2f(S[t][1]) * inv0;
            float p2 = ex2f(S[t][2]) * inv1, p3 = ex2f(S[t][3]) * inv1;
            int col = t * 8 + 2 * gc;
            *(float2*)&wr0[col] = make_float2(p0, p1);
            *(float2*)&wr1[col] = make_float2(p2, p3);
            Ph[t][0] = packh2(p0, p1);     // row gid,  k-cols 2gc,2gc+1 of tile t
            Ph[t][1] = packh2(p2, p3);     // row gid+8
        }

        // ---- Acc += P * V  (chunk c uses tiles 2c, 2c+1; no permutation) ----
        #pragma unroll
        for (int c = 0; c < 4; c++) {
            #pragma unroll
            for (int t = 0; t < 8; t++) {
                uint2 bv = vb[(c * 8 + t) * 32 + lane];
                mma_f16(Acc[t], Ph[2 * c][0], Ph[2 * c][1],
                        Ph[2 * c + 1][0], Ph[2 * c + 1][1], bv.x, bv.y);
            }
        }
    }

    // ---- a: already normalized (P normalized before PV), warp-local store ----
    {
        float* ar0 = out_a + ((size_t)(b * SS + qblk * BQ + warp * 16 + gid)) * DF
                   + hh * HD;
        float* ar1 = ar0 + (size_t)8 * DF;
        #pragma unroll
        for (int t = 0; t < 8; t++) {
            int col = t * 8 + 2 * gc;
            *(float2*)&ar0[col] = make_float2(Acc[t][0], Acc[t][1]);
            *(float2*)&ar1[col] = make_float2(Acc[t][2], Acc[t][3]);
        }
    }
}

extern "C" void kernel_launch(void* const* d_in, const int* in_sizes, int n_in,
                              void* d_out, int out_size)
{
    (void)in_sizes; (void)n_in; (void)out_size;
    const float* q = (const float*)d_in[0];
    const float* k = (const float*)d_in[1];
    const float* v = (const float*)d_in[2];

    float* out_a = (float*)d_out;
    float* out_w = out_a + (size_t)BB * SS * DF;  // w follows a

    shuffle_kvh_kernel<<<(BB * HH * NBLK * 1024) / NT, NT>>>(k, v);
    shuffle_qh_kernel<<<(BB * HH * NQB * 1024) / NT, NT>>>(q);

    cudaFuncSetAttribute(attn_mma_kernel,
                         cudaFuncAttributeMaxDynamicSharedMemorySize, SM_TOTAL);
    dim3 grid(NQB, HH, BB);   // (32, 16, 4) = 2048 CTAs
    attn_mma_kernel<<<grid, NT, SM_TOTAL>>>(out_a, out_w);
}